// round 1
// baseline (speedup 1.0000x reference)
#include <cuda_runtime.h>

#define N_NODES 100000
#define N_EDGES 3200000
#define D       64
#define NH      128

// Scratch (allocation-free rule: __device__ globals)
__device__ float g_A[(size_t)N_NODES * NH];    // 51.2 MB: W1[:, :64] @ z[n] + b1
__device__ float g_B[(size_t)N_NODES * NH];    // 51.2 MB: W1[:, 64:] @ z[n]
__device__ float g_WT[64 * 256];               // fused transposed weights

// ---------------------------------------------------------------------------
// Kernel 0: build WT[k][jj]:  jj<128 -> W1[jj][k]   (A half, k = 0..63)
//                             jj>=128 -> W1[jj-128][64+k] (B half)
// ---------------------------------------------------------------------------
__global__ void build_wt(const float* __restrict__ W1) {
    int k  = blockIdx.x;    // 0..63
    int jj = threadIdx.x;   // 0..255
    float v = (jj < 128) ? W1[jj * NH + k] : W1[(jj - 128) * NH + 64 + k];
    g_WT[k * 256 + jj] = v;
}

// ---------------------------------------------------------------------------
// Kernel 1: node GEMM.  Each block: 32 nodes x 256 outputs (A:128 | B:128).
// 256 threads, each owns 8 nodes x 1 float4 of outputs (32 accumulators).
// WT staged through smem in two 32-k chunks (40 KB static smem total).
// ---------------------------------------------------------------------------
__global__ void node_gemm(const float* __restrict__ z, const float* __restrict__ b1) {
    __shared__ float sZ[32 * 64];    // 8 KB
    __shared__ float sW[32 * 256];   // 32 KB

    const int tid      = threadIdx.x;
    const int nodeBase = blockIdx.x * 32;

    // load z tile (32 nodes x 64 feats), coalesced
    #pragma unroll
    for (int t = 0; t < 8; t++)
        sZ[tid + t * 256] = z[(size_t)nodeBase * D + tid + t * 256];

    const int j4 = tid & 63;          // float4 column group 0..63 (256 outputs)
    const int nb = (tid >> 6) * 8;    // node sub-base 0,8,16,24

    float4 acc[8];
    #pragma unroll
    for (int n = 0; n < 8; n++) acc[n] = make_float4(0.f, 0.f, 0.f, 0.f);

    #pragma unroll
    for (int kc = 0; kc < 2; kc++) {
        __syncthreads();   // (iter 0: also orders sZ fill; iter 1: protects sW reuse)
        #pragma unroll
        for (int t = 0; t < 32; t++)
            sW[tid + t * 256] = g_WT[kc * 32 * 256 + tid + t * 256];
        __syncthreads();

        #pragma unroll
        for (int kk = 0; kk < 32; kk++) {
            float4 w = ((const float4*)sW)[kk * 64 + j4];
            #pragma unroll
            for (int n = 0; n < 8; n++) {
                float zv = sZ[(nb + n) * 64 + kc * 32 + kk];
                acc[n].x += w.x * zv;
                acc[n].y += w.y * zv;
                acc[n].z += w.z * zv;
                acc[n].w += w.w * zv;
            }
        }
    }

    if (j4 < 32) {  // A half: add b1
        float4 bv = ((const float4*)b1)[j4];
        #pragma unroll
        for (int n = 0; n < 8; n++) {
            int node = nodeBase + nb + n;
            float4 o = acc[n];
            o.x += bv.x; o.y += bv.y; o.z += bv.z; o.w += bv.w;
            ((float4*)(g_A + (size_t)node * NH))[j4] = o;
        }
    } else {        // B half
        #pragma unroll
        for (int n = 0; n < 8; n++) {
            int node = nodeBase + nb + n;
            ((float4*)(g_B + (size_t)node * NH))[j4 - 32] = acc[n];
        }
    }
}

// ---------------------------------------------------------------------------
// Kernel 2: edge pass. out[e] = W2 . relu(A[row[e]] + B[col[e]]) + b2
// 8 lanes per edge, 4 edges per warp. Each lane: 4x LDG.128 from A-row +
// 4x from B-row (contiguous 128B per 8-lane group per step). shfl reduce.
// ---------------------------------------------------------------------------
__global__ void edge_kernel(const int* __restrict__ row, const int* __restrict__ col,
                            const float* __restrict__ W2, const float* __restrict__ b2,
                            float* __restrict__ out) {
    const int lane = threadIdx.x & 31;
    const int warp = threadIdx.x >> 5;
    const int g    = lane >> 3;   // edge slot within warp (0..3)
    const int i    = lane & 7;    // lane within edge (0..7)

    const long e = (long)blockIdx.x * 32 + warp * 4 + g;
    if (e >= N_EDGES) return;

    // hoisted W2 chunks for this lane (lane i covers j4 = q*8 + i)
    float4 w[4];
    #pragma unroll
    for (int q = 0; q < 4; q++)
        w[q] = ((const float4*)W2)[q * 8 + i];

    const int r = row[e];
    const int c = col[e];
    const float4* __restrict__ Ar = (const float4*)(g_A + (size_t)r * NH);
    const float4* __restrict__ Bc = (const float4*)(g_B + (size_t)c * NH);

    float4 a[4], b[4];
    #pragma unroll
    for (int q = 0; q < 4; q++) { a[q] = Ar[q * 8 + i]; b[q] = Bc[q * 8 + i]; }

    float s = 0.f;
    #pragma unroll
    for (int q = 0; q < 4; q++) {
        s += w[q].x * fmaxf(a[q].x + b[q].x, 0.f);
        s += w[q].y * fmaxf(a[q].y + b[q].y, 0.f);
        s += w[q].z * fmaxf(a[q].z + b[q].z, 0.f);
        s += w[q].w * fmaxf(a[q].w + b[q].w, 0.f);
    }

    // reduce across the 8 lanes of this edge
    s += __shfl_xor_sync(0xffffffffu, s, 1);
    s += __shfl_xor_sync(0xffffffffu, s, 2);
    s += __shfl_xor_sync(0xffffffffu, s, 4);

    if (i == 0) out[e] = s + b2[0];
}

// ---------------------------------------------------------------------------
extern "C" void kernel_launch(void* const* d_in, const int* in_sizes, int n_in,
                              void* d_out, int out_size) {
    const float* z   = (const float*)d_in[0];
    const int*   row = (const int*)  d_in[1];
    const int*   col = (const int*)  d_in[2];
    const float* W1  = (const float*)d_in[3];
    const float* b1  = (const float*)d_in[4];
    const float* W2  = (const float*)d_in[5];
    const float* b2  = (const float*)d_in[6];
    float* out = (float*)d_out;

    build_wt<<<64, 256>>>(W1);
    node_gemm<<<N_NODES / 32, 256>>>(z, b1);          // 3125 blocks
    edge_kernel<<<N_EDGES / 32, 256>>>(row, col, W2, b2, out);  // 100000 blocks
}

// round 2
// speedup vs baseline: 1.3881x; 1.3881x over previous
#include <cuda_runtime.h>
#include <cuda_fp16.h>

#define N_NODES 100000
#define N_EDGES 3200000
#define D       64
#define NH      128

// Scratch (allocation-free rule: __device__ globals)
__device__ __half g_Ah[(size_t)N_NODES * NH];   // 25.6 MB: W1[:, :64] @ z[n] + b1   (fp16)
__device__ __half g_Bh[(size_t)N_NODES * NH];   // 25.6 MB: W1[:, 64:] @ z[n]        (fp16)
__device__ float  g_WT[64 * 256];               // fused transposed weights

// ---------------------------------------------------------------------------
// Kernel 0: build WT[k][jj]:  jj<128 -> W1[jj][k]   (A half, k = 0..63)
//                             jj>=128 -> W1[jj-128][64+k] (B half)
// ---------------------------------------------------------------------------
__global__ void build_wt(const float* __restrict__ W1) {
    int k  = blockIdx.x;    // 0..63
    int jj = threadIdx.x;   // 0..255
    float v = (jj < 128) ? W1[jj * NH + k] : W1[(jj - 128) * NH + 64 + k];
    g_WT[k * 256 + jj] = v;
}

// ---------------------------------------------------------------------------
// Kernel 1: node GEMM.  Each block: 32 nodes x 256 outputs (A:128 | B:128).
// 256 threads, each owns 8 nodes x 1 float4 of outputs (32 fp32 accumulators).
// z read from smem via float4 broadcast (1 phase per 4 kk per node) so the
// inner loop is FFMA-bound, not LDS-bound. Results stored as fp16.
// ---------------------------------------------------------------------------
__global__ void node_gemm(const float* __restrict__ z, const float* __restrict__ b1) {
    __shared__ float sZ[32 * 64];    // 8 KB
    __shared__ float sW[32 * 256];   // 32 KB

    const int tid      = threadIdx.x;
    const int nodeBase = blockIdx.x * 32;

    // load z tile (32 nodes x 64 feats), coalesced
    #pragma unroll
    for (int t = 0; t < 8; t++)
        sZ[tid + t * 256] = z[(size_t)nodeBase * D + tid + t * 256];

    const int j4 = tid & 63;          // float4 column group 0..63 (256 outputs)
    const int nb = (tid >> 6) * 8;    // node sub-base 0,8,16,24

    const float4* sZ4 = (const float4*)sZ;   // [32 nodes][16 float4]
    const float4* sW4 = (const float4*)sW;   // [32 k][64 float4]

    float4 acc[8];
    #pragma unroll
    for (int n = 0; n < 8; n++) acc[n] = make_float4(0.f, 0.f, 0.f, 0.f);

    #pragma unroll
    for (int kc = 0; kc < 2; kc++) {
        __syncthreads();   // (iter 0: also orders sZ fill; iter 1: protects sW reuse)
        #pragma unroll
        for (int t = 0; t < 32; t++)
            sW[tid + t * 256] = g_WT[kc * 32 * 256 + tid + t * 256];
        __syncthreads();

        #pragma unroll
        for (int kk4 = 0; kk4 < 8; kk4++) {
            float4 zv[8];
            #pragma unroll
            for (int n = 0; n < 8; n++)
                zv[n] = sZ4[(nb + n) * 16 + kc * 8 + kk4];   // broadcast LDS.128

            #pragma unroll
            for (int u = 0; u < 4; u++) {
                float4 w = sW4[(kk4 * 4 + u) * 64 + j4];
                #pragma unroll
                for (int n = 0; n < 8; n++) {
                    float zs = (u == 0) ? zv[n].x : (u == 1) ? zv[n].y
                             : (u == 2) ? zv[n].z : zv[n].w;
                    acc[n].x += w.x * zs;
                    acc[n].y += w.y * zs;
                    acc[n].z += w.z * zs;
                    acc[n].w += w.w * zs;
                }
            }
        }
    }

    // epilogue: (+b1 for A half), convert to fp16, packed 8B store
    if (j4 < 32) {
        float4 bv = ((const float4*)b1)[j4];
        #pragma unroll
        for (int n = 0; n < 8; n++) {
            int node = nodeBase + nb + n;
            float4 o = acc[n];
            o.x += bv.x; o.y += bv.y; o.z += bv.z; o.w += bv.w;
            __half2 h0 = __floats2half2_rn(o.x, o.y);
            __half2 h1 = __floats2half2_rn(o.z, o.w);
            uint2 pk;
            pk.x = *(const unsigned int*)&h0;
            pk.y = *(const unsigned int*)&h1;
            ((uint2*)(g_Ah + (size_t)node * NH))[j4] = pk;
        }
    } else {
        #pragma unroll
        for (int n = 0; n < 8; n++) {
            int node = nodeBase + nb + n;
            float4 o = acc[n];
            __half2 h0 = __floats2half2_rn(o.x, o.y);
            __half2 h1 = __floats2half2_rn(o.z, o.w);
            uint2 pk;
            pk.x = *(const unsigned int*)&h0;
            pk.y = *(const unsigned int*)&h1;
            ((uint2*)(g_Bh + (size_t)node * NH))[j4 - 32] = pk;
        }
    }
}

// ---------------------------------------------------------------------------
// Kernel 2: edge pass. out[e] = W2 . relu(A[row[e]] + B[col[e]]) + b2
// fp16 tables, fp32 math. 8 lanes per edge, 4 edges per warp. Each lane:
// 2x LDG.128 from A-row + 2x from B-row (contiguous 128B per 8-lane group
// per step). shfl reduce across 8 lanes.
// ---------------------------------------------------------------------------
__global__ void edge_kernel(const int* __restrict__ row, const int* __restrict__ col,
                            const float* __restrict__ W2, const float* __restrict__ b2,
                            float* __restrict__ out) {
    const int lane = threadIdx.x & 31;
    const int warp = threadIdx.x >> 5;
    const int g    = lane >> 3;   // edge slot within warp (0..3)
    const int i    = lane & 7;    // lane within edge (0..7)

    const long e = (long)blockIdx.x * 32 + warp * 4 + g;
    if (e >= N_EDGES) return;

    // hoisted W2 for this lane: groups i and 8+i of 8 halves each
    float w[2][8];
    #pragma unroll
    for (int q = 0; q < 2; q++)
        #pragma unroll
        for (int t = 0; t < 8; t++)
            w[q][t] = W2[(q * 8 + i) * 8 + t];

    const int r = row[e];
    const int c = col[e];
    const uint4* __restrict__ Ar = (const uint4*)(g_Ah + (size_t)r * NH);
    const uint4* __restrict__ Bc = (const uint4*)(g_Bh + (size_t)c * NH);

    float s = 0.f;
    #pragma unroll
    for (int q = 0; q < 2; q++) {
        uint4 av = Ar[q * 8 + i];   // 8 halves
        uint4 bv = Bc[q * 8 + i];
        const __half2* ah = (const __half2*)&av;
        const __half2* bh = (const __half2*)&bv;
        #pragma unroll
        for (int t = 0; t < 4; t++) {
            float2 af = __half22float2(ah[t]);
            float2 bf = __half22float2(bh[t]);
            s += w[q][2 * t]     * fmaxf(af.x + bf.x, 0.f);
            s += w[q][2 * t + 1] * fmaxf(af.y + bf.y, 0.f);
        }
    }

    // reduce across the 8 lanes of this edge
    s += __shfl_xor_sync(0xffffffffu, s, 1);
    s += __shfl_xor_sync(0xffffffffu, s, 2);
    s += __shfl_xor_sync(0xffffffffu, s, 4);

    if (i == 0) out[e] = s + b2[0];
}

// ---------------------------------------------------------------------------
extern "C" void kernel_launch(void* const* d_in, const int* in_sizes, int n_in,
                              void* d_out, int out_size) {
    const float* z   = (const float*)d_in[0];
    const int*   row = (const int*)  d_in[1];
    const int*   col = (const int*)  d_in[2];
    const float* W1  = (const float*)d_in[3];
    const float* b1  = (const float*)d_in[4];
    const float* W2  = (const float*)d_in[5];
    const float* b2  = (const float*)d_in[6];
    float* out = (float*)d_out;

    build_wt<<<64, 256>>>(W1);
    node_gemm<<<N_NODES / 32, 256>>>(z, b1);                    // 3125 blocks
    edge_kernel<<<N_EDGES / 32, 256>>>(row, col, W2, b2, out);  // 100000 blocks
}